// round 13
// baseline (speedup 1.0000x reference)
#include <cuda_runtime.h>
#include <cstdint>

// Problem constants
#define BATCH     64
#define NPER      786432
#define VPER      (NPER / 4)              // 196608 int4 per row
#define LEVELS    256
#define HTHREADS  256
#define NCTA      592                     // exactly 4 CTAs on each of 148 SMs
#define BLKV      256                     // int4 per work block (1 CTA iteration)
#define NBLK      (BATCH * VPER / BLKV)   // 49152 work blocks total
#define ROWBLK    (VPER / BLKV)           // 768 blocks per row

// Statically zero; every launch returns them to zero -> graph-replay safe.
__device__ unsigned int g_hist[BATCH * LEVELS];
__device__ unsigned int g_cnt[BATCH];     // arrival tickets per row
__device__ unsigned int g_flag[BATCH];    // row-complete flag
__device__ unsigned int g_done[BATCH];    // broadcast-done tickets

// CTA index owning work block g (inverse of lo_blk(k) = floor(k*NBLK/NCTA)).
__device__ __forceinline__ unsigned cta_of(unsigned g) {
    return (unsigned)(((unsigned long long)(g + 1) * NCTA - 1ull) / NBLK);
}

// ---------------------------------------------------------------------------
// Balanced fused kernel: 592 CTAs (one full 4/SM wave -> spin deadlock-free),
// even block partition (83-84 blocks/CTA). A CTA spans at most 2 rows; it
// flushes its smem histogram per row-segment. Row release uses analytically
// computed arrival counts; the arrival ticket selects the broadcast bin slice.
// Mainloop body identical to the proven round-11 schedule (unroll 4, REDs).
// ---------------------------------------------------------------------------
__global__ void __launch_bounds__(HTHREADS, 4)
fused_kernel(const int4* __restrict__ x, float4* __restrict__ out) {
    __shared__ unsigned int sh[LEVELS * 32];   // 32 KB
    __shared__ unsigned int s_tick[2], s_cnt[2];

    const unsigned tid  = threadIdx.x;
    const unsigned lane = tid & 31u;
    unsigned int hbase = (unsigned int)__cvta_generic_to_shared(sh) + (lane << 2);

    const unsigned k = blockIdx.x;
    const unsigned lo_blk = (unsigned)((unsigned long long)k * NBLK / NCTA);
    const unsigned hi_blk = (unsigned)((unsigned long long)(k + 1) * NBLK / NCTA);
    const unsigned row0 = lo_blk / ROWBLK;
    const unsigned row1 = (hi_blk - 1u) / ROWBLK;
    const int nrows = (int)(row1 - row0) + 1;      // 1 or 2

    // ---- Phase 1: histogram per row-segment ----
    for (unsigned r = row0; r <= row1; r++) {
        #pragma unroll
        for (int i = tid; i < LEVELS * 32; i += HTHREADS) sh[i] = 0u;
        __syncthreads();

        const unsigned s = (lo_blk > r * ROWBLK) ? lo_blk : r * ROWBLK;
        const unsigned e = (hi_blk < (r + 1u) * ROWBLK) ? hi_blk : (r + 1u) * ROWBLK;
        const int iters = (int)(e - s);            // <= 84
        const int4* __restrict__ blk = x + (size_t)s * BLKV;

        #pragma unroll 4
        for (int it = 0; it < iters; it++) {
            int4 v = blk[it * HTHREADS + tid];
            asm volatile("red.shared.add.u32 [%0], %1;"
                         :: "r"(hbase + ((unsigned)v.x << 7)), "r"(1u) : "memory");
            asm volatile("red.shared.add.u32 [%0], %1;"
                         :: "r"(hbase + ((unsigned)v.y << 7)), "r"(1u) : "memory");
            asm volatile("red.shared.add.u32 [%0], %1;"
                         :: "r"(hbase + ((unsigned)v.z << 7)), "r"(1u) : "memory");
            asm volatile("red.shared.add.u32 [%0], %1;"
                         :: "r"(hbase + ((unsigned)v.w << 7)), "r"(1u) : "memory");
        }
        __syncthreads();

        // reduce 32 lane-copies of bin tid (rotated -> conflict-free), REDG
        unsigned int acc = 0;
        #pragma unroll
        for (int c = 0; c < 32; c++) acc += sh[tid * 32 + ((c + tid) & 31u)];
        atomicAdd(&g_hist[r * LEVELS + tid], acc);
        __syncthreads();                           // sh reused next segment
    }

    // ---- Phase 2: publish, then arrive at ALL touched rows before any spin ----
    __threadfence();
    __syncthreads();
    if (tid == 0) {
        for (int ri = 0; ri < nrows; ri++) {
            unsigned r = row0 + ri;
            unsigned cnt = cta_of(r * ROWBLK + ROWBLK - 1u) - cta_of(r * ROWBLK) + 1u;
            unsigned t = atomicAdd(&g_cnt[r], 1u);
            s_tick[ri] = t;
            s_cnt[ri]  = cnt;
            if (t == cnt - 1u) atomicExch(&g_flag[r], 1u);
        }
    }
    __syncthreads();

    // ---- Phase 3: per touched row, spin-release then broadcast my bin slice ----
    for (int ri = 0; ri < nrows; ri++) {
        const unsigned r = row0 + ri;
        if (tid == 0) {
            while (*(volatile unsigned*)&g_flag[r] == 0u) __nanosleep(64);
        }
        __syncthreads();
        __threadfence();                           // acquire: row r complete

        const unsigned cnt = s_cnt[ri];
        const unsigned t   = s_tick[ri];
        const unsigned lob = (t * LEVELS) / cnt;
        const unsigned hib = ((t + 1u) * LEVELS) / cnt;
        const unsigned nb  = hib - lob;            // ~23-29 bins

        float* shf = (float*)sh;
        if (tid < nb) {
            unsigned g = r * LEVELS + lob + tid;
            shf[tid] = (float)g_hist[g];
            g_hist[g] = 0u;                        // disjoint slice -> safe reset
        }
        __syncthreads();

        float4* __restrict__ dst =
            out + ((size_t)r * LEVELS + (size_t)lob) * (LEVELS / 4);
        const int total = (int)nb * (LEVELS / 4);
        for (int q = tid; q < total; q += HTHREADS) {
            float v = shf[q >> 6];
            dst[q] = make_float4(v, v, v, v);
        }
        __syncthreads();                           // shf reused next row

        if (tid == 0) {
            __threadfence();
            unsigned d = atomicAdd(&g_done[r], 1u);
            if (d == cnt - 1u) {                   // last finisher resets row state
                g_cnt[r]  = 0u;
                g_flag[r] = 0u;
                g_done[r] = 0u;
                __threadfence();
            }
        }
    }
}

// ---------------------------------------------------------------------------
extern "C" void kernel_launch(void* const* d_in, const int* in_sizes, int n_in,
                              void* d_out, int out_size) {
    const int4* x = (const int4*)d_in[0];
    float4* out = (float4*)d_out;

    fused_kernel<<<NCTA, HTHREADS>>>(x, out);
}

// round 14
// speedup vs baseline: 1.0899x; 1.0899x over previous
#include <cuda_runtime.h>
#include <cstdint>

// Problem constants
#define BATCH     64
#define NPER      786432
#define VPER      (NPER / 4)             // 196608 int4 per row
#define LEVELS    256
#define HTHREADS  256
#define NCTA      592                    // exactly 4 CTAs per SM, one wave
#define UITERS    48                     // int4 loop iterations per unit (CONST)
#define UNIT_V    (UITERS * HTHREADS)    // 12288 int4 per unit
#define UNITS_PER_ROW (VPER / UNIT_V)    // 16
#define NUNITS    (BATCH * UNITS_PER_ROW)// 1024
#define NBCAST    512                    // broadcast tasks: 64 rows x 8 slices

// Statically zero; every launch returns all of these to zero.
__device__ unsigned int g_hist[BATCH * LEVELS];
__device__ unsigned int g_work;           // hist-unit ticket
__device__ unsigned int g_cnt[BATCH];     // units completed per row
__device__ unsigned int g_flag[BATCH];    // row-complete flag
__device__ unsigned int g_bdone;          // broadcast completions

// ---------------------------------------------------------------------------
// Persistent fused kernel, dynamic unit queue.
// Co-residency: smem 32KB -> 6/SM cap, launch_bounds(256,4) -> regs<=64 ->
// 4 CTAs/SM guaranteed; 592 = 4*148 -> the whole grid is ONE resident wave,
// so the broadcast spin (raised during the co-resident hist phase) is safe.
// Inner hist loop: byte-identical shape to round 11 (const trip, unroll 4).
// ---------------------------------------------------------------------------
__global__ void __launch_bounds__(HTHREADS, 4)
fused_kernel(const int4* __restrict__ x, float4* __restrict__ out) {
    __shared__ unsigned int sh[LEVELS * 32];   // 32 KB
    __shared__ unsigned int s_unit;

    const unsigned tid  = threadIdx.x;
    const unsigned lane = tid & 31u;
    unsigned int hbase = (unsigned int)__cvta_generic_to_shared(sh) + (lane << 2);

    // ---- Phase 1: drain the unit queue ----
    for (;;) {
        if (tid == 0) s_unit = atomicAdd(&g_work, 1u);
        __syncthreads();                      // also orders reuse of sh below
        const unsigned u = s_unit;
        if (u >= NUNITS) break;
        const unsigned row = u / UNITS_PER_ROW;

        #pragma unroll
        for (int i = tid; i < LEVELS * 32; i += HTHREADS) sh[i] = 0u;
        __syncthreads();

        const int4* __restrict__ blk = x + (size_t)u * UNIT_V;

        #pragma unroll 4
        for (int it = 0; it < UITERS; it++) {
            int4 v = blk[it * HTHREADS + tid];
            asm volatile("red.shared.add.u32 [%0], %1;"
                         :: "r"(hbase + ((unsigned)v.x << 7)), "r"(1u) : "memory");
            asm volatile("red.shared.add.u32 [%0], %1;"
                         :: "r"(hbase + ((unsigned)v.y << 7)), "r"(1u) : "memory");
            asm volatile("red.shared.add.u32 [%0], %1;"
                         :: "r"(hbase + ((unsigned)v.z << 7)), "r"(1u) : "memory");
            asm volatile("red.shared.add.u32 [%0], %1;"
                         :: "r"(hbase + ((unsigned)v.w << 7)), "r"(1u) : "memory");
        }
        __syncthreads();

        // reduce 32 lane-copies of bin tid (rotated -> conflict-free), REDG
        unsigned int acc = 0;
        #pragma unroll
        for (int c = 0; c < 32; c++) acc += sh[tid * 32 + ((c + tid) & 31u)];
        atomicAdd(&g_hist[row * LEVELS + tid], acc);

        __threadfence();                      // publish REDG
        __syncthreads();                      // whole CTA published
        if (tid == 0) {
            unsigned t = atomicAdd(&g_cnt[row], 1u);
            if (t == UNITS_PER_ROW - 1u) atomicExch(&g_flag[row], 1u);
        }
    }

    // ---- Phase 2: broadcast task k = blockIdx.x (rows x 8 slices) ----
    const unsigned k = blockIdx.x;
    if (k >= NBCAST) return;                  // spare CTAs exit (no one waits)

    const unsigned row   = k >> 3;
    const unsigned slice = (k & 7u) * 32u;    // 32 bins per task

    if (tid == 0) {
        while (*(volatile unsigned*)&g_flag[row] == 0u) __nanosleep(64);
    }
    __syncthreads();
    __threadfence();                          // acquire: row hist complete

    float* shf = (float*)sh;
    const unsigned binBase = row * LEVELS + slice;
    if (tid < 32) {
        shf[tid] = (float)g_hist[binBase + tid];
        g_hist[binBase + tid] = 0u;           // disjoint slice -> safe reset
    }
    __syncthreads();

    float4* __restrict__ dst =
        out + ((size_t)row * LEVELS + (size_t)slice) * (LEVELS / 4);
    #pragma unroll
    for (int q = tid; q < 32 * (LEVELS / 4); q += HTHREADS) {
        float v = shf[q >> 6];
        dst[q] = make_float4(v, v, v, v);
    }

    // last broadcaster resets queue/sync state for the next graph replay
    if (tid == 0) {
        __threadfence();
        unsigned d = atomicAdd(&g_bdone, 1u);
        if (d == NBCAST - 1u) {
            g_work = 0u;
            for (int r = 0; r < BATCH; r++) { g_cnt[r] = 0u; g_flag[r] = 0u; }
            g_bdone = 0u;
            __threadfence();
        }
    }
}

// ---------------------------------------------------------------------------
extern "C" void kernel_launch(void* const* d_in, const int* in_sizes, int n_in,
                              void* d_out, int out_size) {
    const int4* x = (const int4*)d_in[0];
    float4* out = (float4*)d_out;

    fused_kernel<<<NCTA, HTHREADS>>>(x, out);
}